// round 5
// baseline (speedup 1.0000x reference)
#include <cuda_runtime.h>

// Problem constants
#define Bb 2
#define Ss 2048
#define Dd 1024
#define Hh 16
#define DK 64
#define Mm (Bb*Ss)   // 4096 rows

// ---------------- scratch (device globals; no allocation allowed) ----------------
__device__ float g_Q[Bb*Hh*Ss*DK];     // [b][h][s][d]
__device__ float g_K[Bb*Hh*Ss*DK];
__device__ float g_V[Bb*Hh*Ss*DK];
__device__ float g_attn[Bb*Ss*Dd];     // [b][s][h*64+d]
__device__ float g_cos[Ss*DK];
__device__ float g_sin[Ss*DK];

// ---------------- RoPE tables ----------------
// cos/sin[s][d] with repeat_interleave(2): index d uses freq j = d>>1
__global__ void rope_table_kernel() {
    int s = blockIdx.x;
    int j = threadIdx.x;                       // 0..31
    double f   = pow(10000.0, -(double)(2*j) / 64.0);
    double ang = (double)s * f;
    float c  = (float)cos(ang);
    float sn = (float)sin(ang);
    g_cos[s*DK + 2*j]     = c;
    g_cos[s*DK + 2*j + 1] = c;
    g_sin[s*DK + 2*j]     = sn;
    g_sin[s*DK + 2*j + 1] = sn;
}

// ---------------- RoPE apply (in-place on Q and K) ----------------
// out[d]    = q[d]*cos[d]    - q[d+32]*sin[d]        (d < 32)
// out[d+32] = q[d+32]*cos[d+32] + q[d]*sin[d+32]
__global__ void rope_apply_kernel() {
    int t   = blockIdx.x * blockDim.x + threadIdx.x;  // 0 .. 2^21-1
    float* P = (blockIdx.y == 0) ? g_Q : g_K;
    int row = t >> 5;                // global row in [b][h][s]
    int d   = t & 31;
    int s   = row & (Ss - 1);
    float q0 = P[row*DK + d];
    float q1 = P[row*DK + d + 32];
    float c0 = g_cos[s*DK + d],      s0 = g_sin[s*DK + d];
    float c1 = g_cos[s*DK + d + 32], s1 = g_sin[s*DK + d + 32];
    P[row*DK + d]      = q0*c0 - q1*s0;
    P[row*DK + d + 32] = q1*c1 + q0*s1;
}

// ---------------- SGEMM (NT): C[m,n] = sum_k A[m,k]*W[n,k] + bias[n] ----------------
// BM=BN=128, BK=8, 256 threads, 8x8 micro-tile per thread, global prefetch.
// csel: 0/1/2 -> write g_Q/g_K/g_V in [b][h][s][d] layout; 3 -> write Cext row-major.
// asel: 0 -> A = Aext; 1 -> A = g_attn.
#define BM 128
#define BN 128
#define BK 8

__global__ __launch_bounds__(256)
void sgemm_kernel(const float* __restrict__ Aext, const float* __restrict__ W,
                  const float* __restrict__ bias, float* __restrict__ Cext,
                  int csel, int asel)
{
    const int Kk = Dd, Nn = Dd;
    const float* A = asel ? (const float*)g_attn : Aext;
    float* C;
    int perm;
    if      (csel == 0) { C = g_Q; perm = 1; }
    else if (csel == 1) { C = g_K; perm = 1; }
    else if (csel == 2) { C = g_V; perm = 1; }
    else                { C = Cext; perm = 0; }

    __shared__ float As[BK][BM + 4];
    __shared__ float Bs[BK][BN + 4];

    int tid  = threadIdx.x;
    int m0   = blockIdx.y * BM;
    int n0   = blockIdx.x * BN;
    int ldr  = tid >> 1;            // 0..127 load row
    int kq   = (tid & 1) * 4;       // 0 or 4

    const float* Ap = A + (size_t)(m0 + ldr) * Kk + kq;
    const float* Bp = W + (size_t)(n0 + ldr) * Kk + kq;

    int tx = tid & 15;              // col group
    int ty = tid >> 4;              // row group

    float acc[8][8];
    #pragma unroll
    for (int i = 0; i < 8; i++)
        #pragma unroll
        for (int j = 0; j < 8; j++) acc[i][j] = 0.f;

    float4 an = *(const float4*)Ap;
    float4 bn = *(const float4*)Bp;
    const int NIT = Kk / BK;        // 128

    for (int kt = 0; kt < NIT; kt++) {
        As[kq+0][ldr] = an.x; As[kq+1][ldr] = an.y;
        As[kq+2][ldr] = an.z; As[kq+3][ldr] = an.w;
        Bs[kq+0][ldr] = bn.x; Bs[kq+1][ldr] = bn.y;
        Bs[kq+2][ldr] = bn.z; Bs[kq+3][ldr] = bn.w;
        __syncthreads();

        if (kt + 1 < NIT) {
            an = *(const float4*)(Ap + (size_t)(kt + 1) * BK);
            bn = *(const float4*)(Bp + (size_t)(kt + 1) * BK);
        }

        #pragma unroll
        for (int kk = 0; kk < BK; kk++) {
            float4 a0 = *(const float4*)&As[kk][ty*4];
            float4 a1 = *(const float4*)&As[kk][ty*4 + 64];
            float4 b0 = *(const float4*)&Bs[kk][tx*4];
            float4 b1 = *(const float4*)&Bs[kk][tx*4 + 64];
            float ar[8] = {a0.x,a0.y,a0.z,a0.w, a1.x,a1.y,a1.z,a1.w};
            float br[8] = {b0.x,b0.y,b0.z,b0.w, b1.x,b1.y,b1.z,b1.w};
            #pragma unroll
            for (int i = 0; i < 8; i++)
                #pragma unroll
                for (int j = 0; j < 8; j++)
                    acc[i][j] += ar[i] * br[j];
        }
        __syncthreads();
    }

    // epilogue: bias + (optional) head-permuted write
    #pragma unroll
    for (int ig = 0; ig < 2; ig++) {
        #pragma unroll
        for (int i = 0; i < 4; i++) {
            int m = m0 + ty*4 + ig*64 + i;
            #pragma unroll
            for (int jg = 0; jg < 2; jg++) {
                int n = n0 + tx*4 + jg*64;
                float4 bv = *(const float4*)&bias[n];
                float4 r;
                r.x = acc[ig*4+i][jg*4+0] + bv.x;
                r.y = acc[ig*4+i][jg*4+1] + bv.y;
                r.z = acc[ig*4+i][jg*4+2] + bv.z;
                r.w = acc[ig*4+i][jg*4+3] + bv.w;
                if (!perm) {
                    *(float4*)&C[(size_t)m * Nn + n] = r;
                } else {
                    int b = m >> 11, s = m & 2047;
                    int h = n >> 6,  d = n & 63;
                    *(float4*)&C[(((size_t)(b*Hh + h)) * Ss + s) * DK + d] = r;
                }
            }
        }
    }
}

// ---------------- causal flash attention (fp32) ----------------
// Block: one (b,h) x 64-query tile. 256 threads = 8 warps, each warp owns 8 query rows.
// Lane owns score columns {lane, lane+32} and output dims {2*lane, 2*lane+1}.
// P staged in warp-private smem so PV is a clean FMA-bound mini-GEMM.
#define FA_SMEM_FLOATS (64*64 + 64*68 + 64*68 + 8*8*64)
#define FA_SMEM_BYTES  (FA_SMEM_FLOATS * 4)

__global__ __launch_bounds__(256)
void flash_kernel()
{
    extern __shared__ float sm[];
    float* qs = sm;                  // [64][64]
    float* ks = sm + 64*64;          // [64][68]  padded
    float* vs = ks + 64*68;          // [64][68]  padded
    float* ps = vs + 64*68;          // [8 warps][8 rows][64]

    int qt   = (gridDim.x - 1) - blockIdx.x;   // long blocks first
    int bh   = blockIdx.y;
    int tid  = threadIdx.x;
    int w    = tid >> 5;
    int lane = tid & 31;

    const float* Qb = g_Q + (size_t)bh * Ss * DK;
    const float* Kb = g_K + (size_t)bh * Ss * DK;
    const float* Vb = g_V + (size_t)bh * Ss * DK;
    int q0 = qt * 64;

    // load Q tile (stride 64, float4)
    for (int i = tid; i < 64*16; i += 256) {
        int r = i >> 4, c4 = i & 15;
        ((float4*)qs)[i] = ((const float4*)(Qb + (size_t)(q0 + r) * DK))[c4];
    }

    float mrow[8], lsum[8]; float2 acc[8];
    #pragma unroll
    for (int r = 0; r < 8; r++) {
        mrow[r] = -1e30f; lsum[r] = 0.f; acc[r] = make_float2(0.f, 0.f);
    }

    for (int kt = 0; kt <= qt; kt++) {
        __syncthreads();  // previous tile fully consumed
        for (int i = tid; i < 64*16; i += 256) {
            int r = i >> 4, c4 = i & 15;
            float4 kv = ((const float4*)(Kb + (size_t)(kt*64 + r) * DK))[c4];
            *(float4*)&ks[r*68 + c4*4] = kv;
            float4 vv = ((const float4*)(Vb + (size_t)(kt*64 + r) * DK))[c4];
            *(float4*)&vs[r*68 + c4*4] = vv;
        }
        __syncthreads();

        // scores: S = Q K^T (8 rows x 64 cols per warp)
        float s0[8], s1[8];
        #pragma unroll
        for (int r = 0; r < 8; r++) { s0[r] = 0.f; s1[r] = 0.f; }
        const float* k0p = &ks[lane * 68];
        const float* k1p = &ks[(lane + 32) * 68];
        #pragma unroll 4
        for (int d4 = 0; d4 < 16; d4++) {
            float4 ka = *(const float4*)(k0p + d4*4);
            float4 kb = *(const float4*)(k1p + d4*4);
            #pragma unroll
            for (int r = 0; r < 8; r++) {
                float4 qv = *(const float4*)&qs[(w*8 + r)*64 + d4*4];
                s0[r] += qv.x*ka.x + qv.y*ka.y + qv.z*ka.z + qv.w*ka.w;
                s1[r] += qv.x*kb.x + qv.y*kb.y + qv.z*kb.z + qv.w*kb.w;
            }
        }

        // online softmax per row
        #pragma unroll
        for (int r = 0; r < 8; r++) {
            int grow = q0 + w*8 + r;
            int kc0  = kt*64 + lane;
            int kc1  = kc0 + 32;
            float v0 = s0[r] * 0.125f;     // 1/sqrt(64)
            float v1 = s1[r] * 0.125f;
            if (kc0 > grow) v0 = -1e30f;
            if (kc1 > grow) v1 = -1e30f;
            float tmax = fmaxf(v0, v1);
            #pragma unroll
            for (int off = 16; off; off >>= 1)
                tmax = fmaxf(tmax, __shfl_xor_sync(0xffffffffu, tmax, off));
            float nm = fmaxf(mrow[r], tmax);
            float p0 = __expf(v0 - nm);
            float p1 = __expf(v1 - nm);
            float rs = p0 + p1;
            #pragma unroll
            for (int off = 16; off; off >>= 1)
                rs += __shfl_xor_sync(0xffffffffu, rs, off);
            float alpha = __expf(mrow[r] - nm);
            lsum[r] = lsum[r] * alpha + rs;
            mrow[r] = nm;
            acc[r].x *= alpha;
            acc[r].y *= alpha;
            ps[(w*8 + r)*64 + lane]      = p0;
            ps[(w*8 + r)*64 + lane + 32] = p1;
        }
        __syncwarp();

        // PV: acc[r][2L..2L+1] += sum_c p[r][c] * V[c][2L..2L+1]
        #pragma unroll 4
        for (int c4 = 0; c4 < 16; c4++) {
            float2 va = *(const float2*)&vs[(c4*4 + 0)*68 + 2*lane];
            float2 vb = *(const float2*)&vs[(c4*4 + 1)*68 + 2*lane];
            float2 vc = *(const float2*)&vs[(c4*4 + 2)*68 + 2*lane];
            float2 vd = *(const float2*)&vs[(c4*4 + 3)*68 + 2*lane];
            #pragma unroll
            for (int r = 0; r < 8; r++) {
                float4 pv = *(const float4*)&ps[(w*8 + r)*64 + c4*4];
                acc[r].x += pv.x*va.x + pv.y*vb.x + pv.z*vc.x + pv.w*vd.x;
                acc[r].y += pv.x*va.y + pv.y*vb.y + pv.z*vc.y + pv.w*vd.y;
            }
        }
    }

    // normalize + write to g_attn in [b][s][h*64+d] layout (coalesced per warp)
    int b = bh >> 4, h = bh & 15;
    #pragma unroll
    for (int r = 0; r < 8; r++) {
        int grow = q0 + w*8 + r;
        float inv = 1.0f / lsum[r];
        float2 o = make_float2(acc[r].x * inv, acc[r].y * inv);
        *(float2*)&g_attn[((size_t)(b*Ss + grow)) * Dd + h*DK + 2*lane] = o;
    }
}

// ---------------- launch ----------------
extern "C" void kernel_launch(void* const* d_in, const int* in_sizes, int n_in,
                              void* d_out, int out_size) {
    const float* x  = (const float*)d_in[0];
    const float* Wq = (const float*)d_in[1];
    const float* bq = (const float*)d_in[2];
    const float* Wk = (const float*)d_in[3];
    const float* bk = (const float*)d_in[4];
    const float* Wv = (const float*)d_in[5];
    const float* bv = (const float*)d_in[6];
    const float* Wo = (const float*)d_in[7];
    const float* bo = (const float*)d_in[8];
    float* out = (float*)d_out;

    cudaFuncSetAttribute(flash_kernel,
                         cudaFuncAttributeMaxDynamicSharedMemorySize, FA_SMEM_BYTES);

    rope_table_kernel<<<Ss, 32>>>();

    dim3 gg(Dd / BN, Mm / BM);   // (8, 32)
    sgemm_kernel<<<gg, 256>>>(x, Wq, bq, nullptr, 0, 0);
    sgemm_kernel<<<gg, 256>>>(x, Wk, bk, nullptr, 1, 0);
    sgemm_kernel<<<gg, 256>>>(x, Wv, bv, nullptr, 2, 0);

    rope_apply_kernel<<<dim3((Bb*Hh*Ss*32) / 256, 2), 256>>>();

    flash_kernel<<<dim3(Ss / 64, Bb*Hh), 256, FA_SMEM_BYTES>>>();

    sgemm_kernel<<<gg, 256>>>(nullptr, Wo, bo, out, 3, 1);
}

// round 11
// speedup vs baseline: 1.3401x; 1.3401x over previous
#include <cuda_runtime.h>
#include <cuda_bf16.h>
#include <cstdint>

// Problem constants
#define Bb 2
#define Ss 2048
#define Dd 1024
#define Hh 16
#define DK 64
#define Mm (Bb*Ss)   // 4096 rows

// ---------------- scratch (device globals; no allocation allowed) ----------------
__device__ float g_Q[Bb*Hh*Ss*DK];
__device__ float g_K[Bb*Hh*Ss*DK];
__device__ float g_V[Bb*Hh*Ss*DK];
__device__ float g_cos[Ss*DK];
__device__ float g_sin[Ss*DK];

// bf16 hi/lo decompositions
__device__ __align__(256) __nv_bfloat16 g_xh[Mm*Dd];
__device__ __align__(256) __nv_bfloat16 g_xl[Mm*Dd];
__device__ __align__(256) __nv_bfloat16 g_ah[Mm*Dd];   // attention output hi
__device__ __align__(256) __nv_bfloat16 g_al[Mm*Dd];   // attention output lo
__device__ __align__(256) __nv_bfloat16 g_wh[4][Dd*Dd];
__device__ __align__(256) __nv_bfloat16 g_wl[4][Dd*Dd];

// ---------------- RoPE tables ----------------
__global__ void rope_table_kernel() {
    int s = blockIdx.x;
    int j = threadIdx.x;                       // 0..31
    double f   = pow(10000.0, -(double)(2*j) / 64.0);
    double ang = (double)s * f;
    float c  = (float)cos(ang);
    float sn = (float)sin(ang);
    g_cos[s*DK + 2*j]     = c;
    g_cos[s*DK + 2*j + 1] = c;
    g_sin[s*DK + 2*j]     = sn;
    g_sin[s*DK + 2*j + 1] = sn;
}

// ---------------- RoPE apply (in-place on Q and K) ----------------
__global__ void rope_apply_kernel() {
    int t   = blockIdx.x * blockDim.x + threadIdx.x;
    float* P = (blockIdx.y == 0) ? g_Q : g_K;
    int row = t >> 5;
    int d   = t & 31;
    int s   = row & (Ss - 1);
    float q0 = P[row*DK + d];
    float q1 = P[row*DK + d + 32];
    float c0 = g_cos[s*DK + d],      s0 = g_sin[s*DK + d];
    float c1 = g_cos[s*DK + d + 32], s1 = g_sin[s*DK + d + 32];
    P[row*DK + d]      = q0*c0 - q1*s0;
    P[row*DK + d + 32] = q1*c1 + q0*s1;
}

// ---------------- fp32 -> bf16 hi/lo split ----------------
__global__ void convert_kernel(const float* __restrict__ src,
                               __nv_bfloat16* __restrict__ hi,
                               __nv_bfloat16* __restrict__ lo, int n4) {
    int t = blockIdx.x * blockDim.x + threadIdx.x;
    if (t >= n4) return;
    float4 v = ((const float4*)src)[t];
    __nv_bfloat16 h0 = __float2bfloat16(v.x), h1 = __float2bfloat16(v.y);
    __nv_bfloat16 h2 = __float2bfloat16(v.z), h3 = __float2bfloat16(v.w);
    __nv_bfloat16 l0 = __float2bfloat16(v.x - __bfloat162float(h0));
    __nv_bfloat16 l1 = __float2bfloat16(v.y - __bfloat162float(h1));
    __nv_bfloat16 l2 = __float2bfloat16(v.z - __bfloat162float(h2));
    __nv_bfloat16 l3 = __float2bfloat16(v.w - __bfloat162float(h3));
    ushort4 hp = make_ushort4(__bfloat16_as_ushort(h0), __bfloat16_as_ushort(h1),
                              __bfloat16_as_ushort(h2), __bfloat16_as_ushort(h3));
    ushort4 lp = make_ushort4(__bfloat16_as_ushort(l0), __bfloat16_as_ushort(l1),
                              __bfloat16_as_ushort(l2), __bfloat16_as_ushort(l3));
    ((ushort4*)hi)[t] = hp;
    ((ushort4*)lo)[t] = lp;
}

// ================= mma.sync bf16x3 GEMM =================
// C[m,n] = sum_k A[m,k]*W[n,k] + bias[n],  M=4096, N=1024, K=1024
// A ~ Ah+Al (bf16), W ~ Bh+Bl (bf16). 3 terms: AhBh + AhBl + AlBh, fp32 acc.
// Tile: BM=128, BN=128, BK=32. 256 threads = 8 warps (2 warp-rows x 4 warp-cols),
// warp tile 64x32 = 4x4 m16n8k16 mma tiles. smem padded stride 40 bf16 ->
// conflict-free LDS.32 fragment loads. cp.async double buffering over 32 stages.

#define G_TB    10240                 // one 128x32 bf16 tile, stride 40 bf16 (80B)
#define G_STAGE (4*G_TB)              // Ah, Al, Bh, Bl
#define G_SMEM  (2*G_STAGE)           // 81920 bytes

#define MMA16816(d, a, b) \
    asm volatile("mma.sync.aligned.m16n8k16.row.col.f32.bf16.bf16.f32 " \
        "{%0,%1,%2,%3}, {%4,%5,%6,%7}, {%8,%9}, {%0,%1,%2,%3};" \
        : "+f"((d)[0]), "+f"((d)[1]), "+f"((d)[2]), "+f"((d)[3]) \
        : "r"((a)[0]), "r"((a)[1]), "r"((a)[2]), "r"((a)[3]), \
          "r"((b)[0]), "r"((b)[1]))

__device__ __forceinline__ uint32_t smem_u32(const void* p) {
    uint32_t a;
    asm("{ .reg .u64 t; cvta.to.shared.u64 t, %1; cvt.u32.u64 %0, t; }" : "=r"(a) : "l"(p));
    return a;
}
#define CPA16(dst, src) \
    asm volatile("cp.async.cg.shared.global [%0], [%1], 16;" :: "r"(dst), "l"(src) : "memory")
#define CPA_COMMIT() asm volatile("cp.async.commit_group;" ::: "memory")
#define CPA_WAIT(n)  asm volatile("cp.async.wait_group %0;" :: "n"(n) : "memory")

__global__ __launch_bounds__(256)
void gemm_mma(const __nv_bfloat16* __restrict__ Ah, const __nv_bfloat16* __restrict__ Al,
              const __nv_bfloat16* __restrict__ Bh, const __nv_bfloat16* __restrict__ Bl,
              const float* __restrict__ bias, float* __restrict__ Cext, int csel)
{
    extern __shared__ char smem[];
    uint32_t sb = smem_u32(smem);
    int tid = threadIdx.x;
    int lane = tid & 31;
    int wid  = tid >> 5;
    int wm = wid & 1;          // warp row: 0/1  (64 rows each)
    int wn = wid >> 1;         // warp col: 0..3 (32 cols each)
    int m0 = blockIdx.y * 128;
    int n0 = blockIdx.x * 128;

    // each thread issues 8 cp.async per stage: tile = i>>9, r = (i>>2)&127, ch = i&3
    auto load_stage = [&](int kt, int buf) {
        int kb = kt * 32;
        uint32_t sbase = sb + buf * G_STAGE;
        #pragma unroll
        for (int it = 0; it < 8; it++) {
            int i    = tid + it * 256;
            int tile = i >> 9;
            int r    = (i >> 2) & 127;
            int ch   = i & 3;
            const __nv_bfloat16* src;
            if (tile == 0)      src = Ah + (size_t)(m0 + r) * Dd + kb + ch * 8;
            else if (tile == 1) src = Al + (size_t)(m0 + r) * Dd + kb + ch * 8;
            else if (tile == 2) src = Bh + (size_t)(n0 + r) * Dd + kb + ch * 8;
            else                src = Bl + (size_t)(n0 + r) * Dd + kb + ch * 8;
            uint32_t dst = sbase + tile * G_TB + r * 80 + ch * 16;
            CPA16(dst, src);
        }
        CPA_COMMIT();
    };

    float acc[4][4][4];
    #pragma unroll
    for (int i = 0; i < 4; i++)
        #pragma unroll
        for (int j = 0; j < 4; j++)
            #pragma unroll
            for (int q = 0; q < 4; q++) acc[i][j][q] = 0.f;

    load_stage(0, 0);

    const int NS = 32;   // 1024 / 32
    int arow = (wm*64 + (lane>>2))*80 + (lane&3)*4;
    int brow = (wn*32 + (lane>>2))*80 + (lane&3)*4;

    for (int s = 0; s < NS; s++) {
        if (s + 1 < NS) { load_stage(s + 1, (s + 1) & 1); CPA_WAIT(1); }
        else            { CPA_WAIT(0); }
        __syncthreads();

        const char* st  = smem + (s & 1) * G_STAGE;
        const char* pAh = st;
        const char* pAl = st + G_TB;
        const char* pBh = st + 2*G_TB;
        const char* pBl = st + 3*G_TB;

        #pragma unroll
        for (int kk = 0; kk < 2; kk++) {
            int ao = arow + kk*32;
            int bo = brow + kk*32;
            uint32_t af[4][4], bh[4][2], bl[4][2];
            #pragma unroll
            for (int i = 0; i < 4; i++) {
                int o = ao + i*1280;
                af[i][0] = *(const uint32_t*)(pAh + o);
                af[i][1] = *(const uint32_t*)(pAh + o + 640);
                af[i][2] = *(const uint32_t*)(pAh + o + 16);
                af[i][3] = *(const uint32_t*)(pAh + o + 656);
            }
            #pragma unroll
            for (int j = 0; j < 4; j++) {
                int o = bo + j*640;
                bh[j][0] = *(const uint32_t*)(pBh + o);
                bh[j][1] = *(const uint32_t*)(pBh + o + 16);
                bl[j][0] = *(const uint32_t*)(pBl + o);
                bl[j][1] = *(const uint32_t*)(pBl + o + 16);
            }
            #pragma unroll
            for (int i = 0; i < 4; i++)
                #pragma unroll
                for (int j = 0; j < 4; j++) {
                    MMA16816(acc[i][j], af[i], bh[j]);   // Ah*Bh
                    MMA16816(acc[i][j], af[i], bl[j]);   // Ah*Bl
                }
            // reload A-lo into same regs, third term
            #pragma unroll
            for (int i = 0; i < 4; i++) {
                int o = ao + i*1280;
                af[i][0] = *(const uint32_t*)(pAl + o);
                af[i][1] = *(const uint32_t*)(pAl + o + 640);
                af[i][2] = *(const uint32_t*)(pAl + o + 16);
                af[i][3] = *(const uint32_t*)(pAl + o + 656);
            }
            #pragma unroll
            for (int i = 0; i < 4; i++)
                #pragma unroll
                for (int j = 0; j < 4; j++)
                    MMA16816(acc[i][j], af[i], bh[j]);   // Al*Bh
        }
        __syncthreads();
    }

    // epilogue: registers -> global, bias added, optional head-permute
    float* Cq = (csel == 0) ? g_Q : (csel == 1) ? g_K : (csel == 2) ? g_V : nullptr;
    #pragma unroll
    for (int i = 0; i < 4; i++) {
        int mrow0 = m0 + wm*64 + i*16 + (lane >> 2);
        #pragma unroll
        for (int j = 0; j < 4; j++) {
            int ncol = n0 + wn*32 + j*8 + (lane & 3)*2;
            float2 bv = *(const float2*)&bias[ncol];
            #pragma unroll
            for (int half = 0; half < 2; half++) {
                int m = mrow0 + half*8;
                float2 v;
                v.x = acc[i][j][half*2 + 0] + bv.x;
                v.y = acc[i][j][half*2 + 1] + bv.y;
                if (csel == 3) {
                    *(float2*)&Cext[(size_t)m * Dd + ncol] = v;
                } else {
                    int b = m >> 11, s2 = m & (Ss - 1);
                    int h = ncol >> 6, d = ncol & 63;
                    *(float2*)&Cq[(((size_t)(b*Hh + h)) * Ss + s2) * DK + d] = v;
                }
            }
        }
    }
}

// ---------------- causal flash attention (fp32) ----------------
#define FA_SMEM_FLOATS (64*64 + 64*68 + 64*68 + 8*8*64)
#define FA_SMEM_BYTES  (FA_SMEM_FLOATS * 4)

__global__ __launch_bounds__(256)
void flash_kernel()
{
    extern __shared__ float sm[];
    float* qs = sm;                  // [64][64]
    float* ks = sm + 64*64;          // [64][68]  padded
    float* vs = ks + 64*68;          // [64][68]  padded
    float* ps = vs + 64*68;          // [8 warps][8 rows][64]

    int qt   = (gridDim.x - 1) - blockIdx.x;   // long blocks first
    int bh   = blockIdx.y;
    int tid  = threadIdx.x;
    int w    = tid >> 5;
    int lane = tid & 31;

    const float* Qb = g_Q + (size_t)bh * Ss * DK;
    const float* Kb = g_K + (size_t)bh * Ss * DK;
    const float* Vb = g_V + (size_t)bh * Ss * DK;
    int q0 = qt * 64;

    for (int i = tid; i < 64*16; i += 256) {
        int r = i >> 4, c4 = i & 15;
        ((float4*)qs)[i] = ((const float4*)(Qb + (size_t)(q0 + r) * DK))[c4];
    }

    float mrow[8], lsum[8]; float2 acc[8];
    #pragma unroll
    for (int r = 0; r < 8; r++) {
        mrow[r] = -1e30f; lsum[r] = 0.f; acc[r] = make_float2(0.f, 0.f);
    }

    for (int kt = 0; kt <= qt; kt++) {
        __syncthreads();
        for (int i = tid; i < 64*16; i += 256) {
            int r = i >> 4, c4 = i & 15;
            float4 kv = ((const float4*)(Kb + (size_t)(kt*64 + r) * DK))[c4];
            *(float4*)&ks[r*68 + c4*4] = kv;
            float4 vv = ((const float4*)(Vb + (size_t)(kt*64 + r) * DK))[c4];
            *(float4*)&vs[r*68 + c4*4] = vv;
        }
        __syncthreads();

        float s0[8], s1[8];
        #pragma unroll
        for (int r = 0; r < 8; r++) { s0[r] = 0.f; s1[r] = 0.f; }
        const float* k0p = &ks[lane * 68];
        const float* k1p = &ks[(lane + 32) * 68];
        #pragma unroll 4
        for (int d4 = 0; d4 < 16; d4++) {
            float4 ka = *(const float4*)(k0p + d4*4);
            float4 kb = *(const float4*)(k1p + d4*4);
            #pragma unroll
            for (int r = 0; r < 8; r++) {
                float4 qv = *(const float4*)&qs[(w*8 + r)*64 + d4*4];
                s0[r] += qv.x*ka.x + qv.y*ka.y + qv.z*ka.z + qv.w*ka.w;
                s1[r] += qv.x*kb.x + qv.y*kb.y + qv.z*kb.z + qv.w*kb.w;
            }
        }

        #pragma unroll
        for (int r = 0; r < 8; r++) {
            int grow = q0 + w*8 + r;
            int kc0  = kt*64 + lane;
            int kc1  = kc0 + 32;
            float v0 = s0[r] * 0.125f;
            float v1 = s1[r] * 0.125f;
            if (kc0 > grow) v0 = -1e30f;
            if (kc1 > grow) v1 = -1e30f;
            float tmax = fmaxf(v0, v1);
            #pragma unroll
            for (int off = 16; off; off >>= 1)
                tmax = fmaxf(tmax, __shfl_xor_sync(0xffffffffu, tmax, off));
            float nm = fmaxf(mrow[r], tmax);
            float p0 = __expf(v0 - nm);
            float p1 = __expf(v1 - nm);
            float rs = p0 + p1;
            #pragma unroll
            for (int off = 16; off; off >>= 1)
                rs += __shfl_xor_sync(0xffffffffu, rs, off);
            float alpha = __expf(mrow[r] - nm);
            lsum[r] = lsum[r] * alpha + rs;
            mrow[r] = nm;
            acc[r].x *= alpha;
            acc[r].y *= alpha;
            ps[(w*8 + r)*64 + lane]      = p0;
            ps[(w*8 + r)*64 + lane + 32] = p1;
        }
        __syncwarp();

        #pragma unroll 4
        for (int c4 = 0; c4 < 16; c4++) {
            float2 va = *(const float2*)&vs[(c4*4 + 0)*68 + 2*lane];
            float2 vb = *(const float2*)&vs[(c4*4 + 1)*68 + 2*lane];
            float2 vc = *(const float2*)&vs[(c4*4 + 2)*68 + 2*lane];
            float2 vd = *(const float2*)&vs[(c4*4 + 3)*68 + 2*lane];
            #pragma unroll
            for (int r = 0; r < 8; r++) {
                float4 pv = *(const float4*)&ps[(w*8 + r)*64 + c4*4];
                acc[r].x += pv.x*va.x + pv.y*vb.x + pv.z*vc.x + pv.w*vd.x;
                acc[r].y += pv.x*va.y + pv.y*vb.y + pv.z*vc.y + pv.w*vd.y;
            }
        }
    }

    // normalize + write bf16 hi/lo for the O-projection GEMM
    int b = bh >> 4, h = bh & 15;
    #pragma unroll
    for (int r = 0; r < 8; r++) {
        int grow = q0 + w*8 + r;
        float inv = 1.0f / lsum[r];
        float ox = acc[r].x * inv, oy = acc[r].y * inv;
        __nv_bfloat16 hx = __float2bfloat16(ox), hy = __float2bfloat16(oy);
        __nv_bfloat16 lx = __float2bfloat16(ox - __bfloat162float(hx));
        __nv_bfloat16 ly = __float2bfloat16(oy - __bfloat162float(hy));
        size_t idx = ((size_t)(b*Ss + grow)) * Dd + h*DK + 2*lane;
        ((ushort2*)g_ah)[idx >> 1] = make_ushort2(__bfloat16_as_ushort(hx), __bfloat16_as_ushort(hy));
        ((ushort2*)g_al)[idx >> 1] = make_ushort2(__bfloat16_as_ushort(lx), __bfloat16_as_ushort(ly));
    }
}

// ---------------- launch ----------------
extern "C" void kernel_launch(void* const* d_in, const int* in_sizes, int n_in,
                              void* d_out, int out_size) {
    const float* x  = (const float*)d_in[0];
    const float* Wq = (const float*)d_in[1];
    const float* bq = (const float*)d_in[2];
    const float* Wk = (const float*)d_in[3];
    const float* bk = (const float*)d_in[4];
    const float* Wv = (const float*)d_in[5];
    const float* bv = (const float*)d_in[6];
    const float* Wo = (const float*)d_in[7];
    const float* bo = (const float*)d_in[8];
    float* out = (float*)d_out;

    cudaFuncSetAttribute(flash_kernel,
                         cudaFuncAttributeMaxDynamicSharedMemorySize, FA_SMEM_BYTES);
    cudaFuncSetAttribute(gemm_mma,
                         cudaFuncAttributeMaxDynamicSharedMemorySize, G_SMEM);

    // resolve device-global addresses host-side
    __nv_bfloat16 *xh, *xl, *ah, *al, *wh, *wl;
    cudaGetSymbolAddress((void**)&xh, g_xh);
    cudaGetSymbolAddress((void**)&xl, g_xl);
    cudaGetSymbolAddress((void**)&ah, g_ah);
    cudaGetSymbolAddress((void**)&al, g_al);
    cudaGetSymbolAddress((void**)&wh, g_wh);
    cudaGetSymbolAddress((void**)&wl, g_wl);

    rope_table_kernel<<<Ss, 32>>>();

    convert_kernel<<<(Mm*Dd/4)/256, 256>>>(x,  xh, xl, Mm*Dd/4);
    convert_kernel<<<(Dd*Dd/4)/256, 256>>>(Wq, wh + 0*(size_t)Dd*Dd, wl + 0*(size_t)Dd*Dd, Dd*Dd/4);
    convert_kernel<<<(Dd*Dd/4)/256, 256>>>(Wk, wh + 1*(size_t)Dd*Dd, wl + 1*(size_t)Dd*Dd, Dd*Dd/4);
    convert_kernel<<<(Dd*Dd/4)/256, 256>>>(Wv, wh + 2*(size_t)Dd*Dd, wl + 2*(size_t)Dd*Dd, Dd*Dd/4);
    convert_kernel<<<(Dd*Dd/4)/256, 256>>>(Wo, wh + 3*(size_t)Dd*Dd, wl + 3*(size_t)Dd*Dd, Dd*Dd/4);

    dim3 gg(Dd / 128, Mm / 128);   // (8, 32)
    gemm_mma<<<gg, 256, G_SMEM>>>(xh, xl, wh + 0*(size_t)Dd*Dd, wl + 0*(size_t)Dd*Dd, bq, nullptr, 0);
    gemm_mma<<<gg, 256, G_SMEM>>>(xh, xl, wh + 1*(size_t)Dd*Dd, wl + 1*(size_t)Dd*Dd, bk, nullptr, 1);
    gemm_mma<<<gg, 256, G_SMEM>>>(xh, xl, wh + 2*(size_t)Dd*Dd, wl + 2*(size_t)Dd*Dd, bv, nullptr, 2);

    rope_apply_kernel<<<dim3((Bb*Hh*Ss*32) / 256, 2), 256>>>();

    flash_kernel<<<dim3(Ss / 64, Bb*Hh), 256, FA_SMEM_BYTES>>>();

    gemm_mma<<<gg, 256, G_SMEM>>>(ah, al, wh + 3*(size_t)Dd*Dd, wl + 3*(size_t)Dd*Dd, bo, out, 3);
}

// round 13
// speedup vs baseline: 2.3783x; 1.7747x over previous
#include <cuda_runtime.h>
#include <cuda_bf16.h>
#include <cstdint>

// Problem constants
#define Bb 2
#define Ss 2048
#define Dd 1024
#define Hh 16
#define DK 64
#define Mm (Bb*Ss)   // 4096 rows

// ---------------- scratch (device globals; no allocation allowed) ----------------
__device__ float g_Q[Bb*Hh*Ss*DK];     // fp32, post-GEMM pre-RoPE
__device__ float g_K[Bb*Hh*Ss*DK];
__device__ float g_cos[Ss*DK];
__device__ float g_sin[Ss*DK];

// bf16 hi/lo decompositions
__device__ __align__(256) __nv_bfloat16 g_xh[Mm*Dd];
__device__ __align__(256) __nv_bfloat16 g_xl[Mm*Dd];
__device__ __align__(256) __nv_bfloat16 g_ah[Mm*Dd];   // attention out hi
__device__ __align__(256) __nv_bfloat16 g_al[Mm*Dd];   // attention out lo
__device__ __align__(256) __nv_bfloat16 g_wh[4][Dd*Dd];
__device__ __align__(256) __nv_bfloat16 g_wl[4][Dd*Dd];
// per-head bf16 hi/lo Q,K (post-RoPE) and V: [b][h][s][d]
__device__ __align__(256) __nv_bfloat16 g_qh[Bb*Hh*Ss*DK];
__device__ __align__(256) __nv_bfloat16 g_ql[Bb*Hh*Ss*DK];
__device__ __align__(256) __nv_bfloat16 g_kh[Bb*Hh*Ss*DK];
__device__ __align__(256) __nv_bfloat16 g_kl[Bb*Hh*Ss*DK];
__device__ __align__(256) __nv_bfloat16 g_vh[Bb*Hh*Ss*DK];
__device__ __align__(256) __nv_bfloat16 g_vl[Bb*Hh*Ss*DK];

// ---------------- common helpers ----------------
__device__ __forceinline__ uint32_t smem_u32(const void* p) {
    uint32_t a;
    asm("{ .reg .u64 t; cvta.to.shared.u64 t, %1; cvt.u32.u64 %0, t; }" : "=r"(a) : "l"(p));
    return a;
}
#define CPA16(dst, src) \
    asm volatile("cp.async.cg.shared.global [%0], [%1], 16;" :: "r"(dst), "l"(src) : "memory")
#define CPA_COMMIT() asm volatile("cp.async.commit_group;" ::: "memory")
#define CPA_WAIT(n)  asm volatile("cp.async.wait_group %0;" :: "n"(n) : "memory")

#define MMA16816(d, a, b) \
    asm volatile("mma.sync.aligned.m16n8k16.row.col.f32.bf16.bf16.f32 " \
        "{%0,%1,%2,%3}, {%4,%5,%6,%7}, {%8,%9}, {%0,%1,%2,%3};" \
        : "+f"((d)[0]), "+f"((d)[1]), "+f"((d)[2]), "+f"((d)[3]) \
        : "r"((a)[0]), "r"((a)[1]), "r"((a)[2]), "r"((a)[3]), \
          "r"((b)[0]), "r"((b)[1]))
#define MMA2(d, a, b0_, b1_) \
    asm volatile("mma.sync.aligned.m16n8k16.row.col.f32.bf16.bf16.f32 " \
        "{%0,%1,%2,%3}, {%4,%5,%6,%7}, {%8,%9}, {%0,%1,%2,%3};" \
        : "+f"((d)[0]), "+f"((d)[1]), "+f"((d)[2]), "+f"((d)[3]) \
        : "r"((a)[0]), "r"((a)[1]), "r"((a)[2]), "r"((a)[3]), \
          "r"(b0_), "r"(b1_))
#define LDSM4(r, a) \
    asm volatile("ldmatrix.sync.aligned.m8n8.x4.shared.b16 {%0,%1,%2,%3}, [%4];" \
        : "=r"((r)[0]), "=r"((r)[1]), "=r"((r)[2]), "=r"((r)[3]) : "r"(a))
#define LDSM4T(r, a) \
    asm volatile("ldmatrix.sync.aligned.m8n8.x4.trans.shared.b16 {%0,%1,%2,%3}, [%4];" \
        : "=r"((r)[0]), "=r"((r)[1]), "=r"((r)[2]), "=r"((r)[3]) : "r"(a))

__device__ __forceinline__ uint32_t pk2(float lo, float hi) {
    __nv_bfloat162 t = __floats2bfloat162_rn(lo, hi);
    return *(uint32_t*)&t;
}

// ---------------- RoPE tables ----------------
__global__ void rope_table_kernel() {
    int s = blockIdx.x;
    int j = threadIdx.x;                       // 0..31
    double f   = pow(10000.0, -(double)(2*j) / 64.0);
    double ang = (double)s * f;
    float c  = (float)cos(ang);
    float sn = (float)sin(ang);
    g_cos[s*DK + 2*j]     = c;
    g_cos[s*DK + 2*j + 1] = c;
    g_sin[s*DK + 2*j]     = sn;
    g_sin[s*DK + 2*j + 1] = sn;
}

// ---------------- RoPE apply: fp32 Q/K -> rotated bf16 hi/lo ----------------
__global__ void rope_apply_kernel() {
    int t   = blockIdx.x * blockDim.x + threadIdx.x;
    const float* P = (blockIdx.y == 0) ? g_Q : g_K;
    __nv_bfloat16* H = (blockIdx.y == 0) ? g_qh : g_kh;
    __nv_bfloat16* L = (blockIdx.y == 0) ? g_ql : g_kl;
    int row = t >> 5;
    int d   = t & 31;
    int s   = row & (Ss - 1);
    float q0 = P[row*DK + d];
    float q1 = P[row*DK + d + 32];
    float c0 = g_cos[s*DK + d],      s0 = g_sin[s*DK + d];
    float c1 = g_cos[s*DK + d + 32], s1 = g_sin[s*DK + d + 32];
    float o0 = q0*c0 - q1*s0;
    float o1 = q1*c1 + q0*s1;
    __nv_bfloat16 h0 = __float2bfloat16(o0);
    __nv_bfloat16 h1 = __float2bfloat16(o1);
    H[row*DK + d]      = h0;
    H[row*DK + d + 32] = h1;
    L[row*DK + d]      = __float2bfloat16(o0 - __bfloat162float(h0));
    L[row*DK + d + 32] = __float2bfloat16(o1 - __bfloat162float(h1));
}

// ---------------- fp32 -> bf16 hi/lo split ----------------
__global__ void convert_kernel(const float* __restrict__ src,
                               __nv_bfloat16* __restrict__ hi,
                               __nv_bfloat16* __restrict__ lo, int n4) {
    int t = blockIdx.x * blockDim.x + threadIdx.x;
    if (t >= n4) return;
    float4 v = ((const float4*)src)[t];
    __nv_bfloat16 h0 = __float2bfloat16(v.x), h1 = __float2bfloat16(v.y);
    __nv_bfloat16 h2 = __float2bfloat16(v.z), h3 = __float2bfloat16(v.w);
    __nv_bfloat16 l0 = __float2bfloat16(v.x - __bfloat162float(h0));
    __nv_bfloat16 l1 = __float2bfloat16(v.y - __bfloat162float(h1));
    __nv_bfloat16 l2 = __float2bfloat16(v.z - __bfloat162float(h2));
    __nv_bfloat16 l3 = __float2bfloat16(v.w - __bfloat162float(h3));
    ushort4 hp = make_ushort4(__bfloat16_as_ushort(h0), __bfloat16_as_ushort(h1),
                              __bfloat16_as_ushort(h2), __bfloat16_as_ushort(h3));
    ushort4 lp = make_ushort4(__bfloat16_as_ushort(l0), __bfloat16_as_ushort(l1),
                              __bfloat16_as_ushort(l2), __bfloat16_as_ushort(l3));
    ((ushort4*)hi)[t] = hp;
    ((ushort4*)lo)[t] = lp;
}

// ================= mma.sync bf16x3 GEMM (V epilogue emits hi/lo) ====
#define G_TB    10240
#define G_STAGE (4*G_TB)
#define G_SMEM  (2*G_STAGE)

__global__ __launch_bounds__(256)
void gemm_mma(const __nv_bfloat16* __restrict__ Ah, const __nv_bfloat16* __restrict__ Al,
              const __nv_bfloat16* __restrict__ Bh, const __nv_bfloat16* __restrict__ Bl,
              const float* __restrict__ bias, float* __restrict__ Cext, int csel)
{
    extern __shared__ char smem[];
    uint32_t sb = smem_u32(smem);
    int tid = threadIdx.x;
    int lane = tid & 31;
    int wid  = tid >> 5;
    int wm = wid & 1;
    int wn = wid >> 1;
    int m0 = blockIdx.y * 128;
    int n0 = blockIdx.x * 128;

    auto load_stage = [&](int kt, int buf) {
        int kb = kt * 32;
        uint32_t sbase = sb + buf * G_STAGE;
        #pragma unroll
        for (int it = 0; it < 8; it++) {
            int i    = tid + it * 256;
            int tile = i >> 9;
            int r    = (i >> 2) & 127;
            int ch   = i & 3;
            const __nv_bfloat16* src;
            if (tile == 0)      src = Ah + (size_t)(m0 + r) * Dd + kb + ch * 8;
            else if (tile == 1) src = Al + (size_t)(m0 + r) * Dd + kb + ch * 8;
            else if (tile == 2) src = Bh + (size_t)(n0 + r) * Dd + kb + ch * 8;
            else                src = Bl + (size_t)(n0 + r) * Dd + kb + ch * 8;
            uint32_t dst = sbase + tile * G_TB + r * 80 + ch * 16;
            CPA16(dst, src);
        }
        CPA_COMMIT();
    };

    float acc[4][4][4];
    #pragma unroll
    for (int i = 0; i < 4; i++)
        #pragma unroll
        for (int j = 0; j < 4; j++)
            #pragma unroll
            for (int q = 0; q < 4; q++) acc[i][j][q] = 0.f;

    load_stage(0, 0);

    const int NS = 32;
    int arow = (wm*64 + (lane>>2))*80 + (lane&3)*4;
    int brow = (wn*32 + (lane>>2))*80 + (lane&3)*4;

    for (int s = 0; s < NS; s++) {
        if (s + 1 < NS) { load_stage(s + 1, (s + 1) & 1); CPA_WAIT(1); }
        else            { CPA_WAIT(0); }
        __syncthreads();

        const char* st  = smem + (s & 1) * G_STAGE;
        const char* pAh = st;
        const char* pAl = st + G_TB;
        const char* pBh = st + 2*G_TB;
        const char* pBl = st + 3*G_TB;

        #pragma unroll
        for (int kk = 0; kk < 2; kk++) {
            int ao = arow + kk*32;
            int bo = brow + kk*32;
            uint32_t af[4][4], bh[4][2], bl[4][2];
            #pragma unroll
            for (int i = 0; i < 4; i++) {
                int o = ao + i*1280;
                af[i][0] = *(const uint32_t*)(pAh + o);
                af[i][1] = *(const uint32_t*)(pAh + o + 640);
                af[i][2] = *(const uint32_t*)(pAh + o + 16);
                af[i][3] = *(const uint32_t*)(pAh + o + 656);
            }
            #pragma unroll
            for (int j = 0; j < 4; j++) {
                int o = bo + j*640;
                bh[j][0] = *(const uint32_t*)(pBh + o);
                bh[j][1] = *(const uint32_t*)(pBh + o + 16);
                bl[j][0] = *(const uint32_t*)(pBl + o);
                bl[j][1] = *(const uint32_t*)(pBl + o + 16);
            }
            #pragma unroll
            for (int i = 0; i < 4; i++)
                #pragma unroll
                for (int j = 0; j < 4; j++) {
                    MMA16816(acc[i][j], af[i], bh[j]);
                    MMA16816(acc[i][j], af[i], bl[j]);
                }
            #pragma unroll
            for (int i = 0; i < 4; i++) {
                int o = ao + i*1280;
                af[i][0] = *(const uint32_t*)(pAl + o);
                af[i][1] = *(const uint32_t*)(pAl + o + 640);
                af[i][2] = *(const uint32_t*)(pAl + o + 16);
                af[i][3] = *(const uint32_t*)(pAl + o + 656);
            }
            #pragma unroll
            for (int i = 0; i < 4; i++)
                #pragma unroll
                for (int j = 0; j < 4; j++)
                    MMA16816(acc[i][j], af[i], bh[j]);
        }
        __syncthreads();
    }

    #pragma unroll
    for (int i = 0; i < 4; i++) {
        int mrow0 = m0 + wm*64 + i*16 + (lane >> 2);
        #pragma unroll
        for (int j = 0; j < 4; j++) {
            int ncol = n0 + wn*32 + j*8 + (lane & 3)*2;
            float2 bv = *(const float2*)&bias[ncol];
            #pragma unroll
            for (int half = 0; half < 2; half++) {
                int m = mrow0 + half*8;
                float2 v;
                v.x = acc[i][j][half*2 + 0] + bv.x;
                v.y = acc[i][j][half*2 + 1] + bv.y;
                if (csel == 3) {
                    *(float2*)&Cext[(size_t)m * Dd + ncol] = v;
                } else {
                    int b = m >> 11, s2 = m & (Ss - 1);
                    int h = ncol >> 6, d = ncol & 63;
                    size_t idx = (((size_t)(b*Hh + h)) * Ss + s2) * DK + d;
                    if (csel == 2) {
                        __nv_bfloat16 hx = __float2bfloat16(v.x), hy = __float2bfloat16(v.y);
                        __nv_bfloat16 lx = __float2bfloat16(v.x - __bfloat162float(hx));
                        __nv_bfloat16 ly = __float2bfloat16(v.y - __bfloat162float(hy));
                        *(ushort2*)&g_vh[idx] = make_ushort2(__bfloat16_as_ushort(hx), __bfloat16_as_ushort(hy));
                        *(ushort2*)&g_vl[idx] = make_ushort2(__bfloat16_as_ushort(lx), __bfloat16_as_ushort(ly));
                    } else {
                        float* Cq = (csel == 0) ? g_Q : g_K;
                        *(float2*)&Cq[idx] = v;
                    }
                }
            }
        }
    }
}

// ================= tensor-core causal flash attention (bf16x3) =================
#define FS_ROWB 144
#define FQ_SZ   (128*FS_ROWB)        // 18432
#define FKV_OFF (2*FQ_SZ)            // 36864
#define FKV_TB  (64*FS_ROWB)         // 9216 per tile
#define FKV_BUF (4*FKV_TB)           // 36864
#define FA_SMEM (FKV_OFF + 2*FKV_BUF) // 110592

__global__ __launch_bounds__(256, 1)
void flash_mma()
{
    extern __shared__ char sm[];
    uint32_t sb = smem_u32(sm);
    int tid = threadIdx.x, lane = tid & 31, w = tid >> 5;
    int qt = (int)(gridDim.x - 1 - blockIdx.x);   // long blocks first
    int bh = blockIdx.y;
    int q0 = qt * 128;
    int KT = 2*qt + 2;

    const __nv_bfloat16* qhp = g_qh + (size_t)bh * Ss * DK;
    const __nv_bfloat16* qlp = g_ql + (size_t)bh * Ss * DK;
    const __nv_bfloat16* khp = g_kh + (size_t)bh * Ss * DK;
    const __nv_bfloat16* klp = g_kl + (size_t)bh * Ss * DK;
    const __nv_bfloat16* vhp = g_vh + (size_t)bh * Ss * DK;
    const __nv_bfloat16* vlp = g_vl + (size_t)bh * Ss * DK;

    auto load_kv = [&](int kt) {
        uint32_t base = sb + FKV_OFF + (kt & 1) * FKV_BUF;
        #pragma unroll
        for (int it = 0; it < 8; it++) {
            int i = tid + it * 256;
            int arr = i >> 9, rem = i & 511, r = rem >> 3, c = rem & 7;
            const __nv_bfloat16* p = (arr == 0) ? khp : (arr == 1) ? klp
                                   : (arr == 2) ? vhp : vlp;
            CPA16(base + arr * FKV_TB + r * FS_ROWB + c * 16,
                  p + (size_t)(kt*64 + r) * DK + c * 8);
        }
        CPA_COMMIT();
    };

    // Q (hi/lo) + KV tile 0, one group
    #pragma unroll
    for (int it = 0; it < 8; it++) {
        int i = tid + it * 256;
        int arr = i >> 10, rem = i & 1023, r = rem >> 3, c = rem & 7;
        CPA16(sb + arr * FQ_SZ + r * FS_ROWB + c * 16,
              (arr ? qlp : qhp) + (size_t)(q0 + r) * DK + c * 8);
    }
    load_kv(0);

    float O[32], sc[32];
    #pragma unroll
    for (int i = 0; i < 32; i++) O[i] = 0.f;
    float mrow[2] = {-1e30f, -1e30f};
    float lsum[2] = {0.f, 0.f};

    int rbase = w * 16;
    int l7 = lane & 7;
    int row0g = q0 + rbase + (lane >> 2);
    uint32_t q_ra = (uint32_t)((rbase + l7 + ((lane >> 3) & 1) * 8) * FS_ROWB + ((lane >> 4) & 1) * 16);
    uint32_t k_rl = (uint32_t)((l7 + ((lane >> 4) & 1) * 8) * FS_ROWB + ((lane >> 3) & 1) * 16);
    uint32_t v_rl = (uint32_t)((l7 + ((lane >> 3) & 1) * 8) * FS_ROWB + ((lane >> 4) & 1) * 16);

    for (int kt = 0; kt < KT; kt++) {
        if (kt + 1 < KT) { load_kv(kt + 1); CPA_WAIT(1); }
        else             { CPA_WAIT(0); }
        __syncthreads();

        uint32_t kvb = sb + FKV_OFF + (kt & 1) * FKV_BUF;
        bool active = (kt*64 <= q0 + rbase + 15);
        if (active) {
            #pragma unroll
            for (int i = 0; i < 32; i++) sc[i] = 0.f;

            // ---- scores: S = Q K^T (bf16x3) ----
            #pragma unroll
            for (int kk = 0; kk < 4; kk++) {
                uint32_t qa = sb + q_ra + kk*32;
                uint32_t aH[4], aL[4];
                LDSM4(aH, qa);
                LDSM4(aL, qa + FQ_SZ);
                #pragma unroll
                for (int np = 0; np < 4; np++) {
                    uint32_t ka = kvb + k_rl + (uint32_t)(np*16*FS_ROWB) + kk*32;
                    uint32_t bH[4], bL[4];
                    LDSM4(bH, ka);
                    LDSM4(bL, ka + FKV_TB);
                    float* s0 = &sc[(2*np)*4];
                    float* s1 = &sc[(2*np+1)*4];
                    MMA2(s0, aH, bH[0], bH[1]);
                    MMA2(s1, aH, bH[2], bH[3]);
                    MMA2(s0, aH, bL[0], bL[1]);
                    MMA2(s1, aH, bL[2], bL[3]);
                    MMA2(s0, aL, bH[0], bH[1]);
                    MMA2(s1, aL, bH[2], bH[3]);
                }
            }

            // ---- online softmax ----
            // FIX R12: mask needed whenever tile's last col exceeds the warp's
            // SMALLEST row (q0+rbase), not its largest. Diagonal tiles of warps
            // with rbase%64==48 previously leaked future columns.
            bool maskt = (kt*64 + 63 > q0 + rbase);
            #pragma unroll
            for (int n = 0; n < 8; n++)
                #pragma unroll
                for (int q = 0; q < 4; q++) {
                    float v = sc[n*4+q] * 0.125f;
                    if (maskt) {
                        int col = kt*64 + n*8 + (lane & 3)*2 + (q & 1);
                        int row = row0g + ((q >> 1) << 3);
                        if (col > row) v = -1e30f;
                    }
                    sc[n*4+q] = v;
                }
            float tm0 = -1e30f, tm1 = -1e30f;
            #pragma unroll
            for (int n = 0; n < 8; n++) {
                tm0 = fmaxf(tm0, fmaxf(sc[n*4+0], sc[n*4+1]));
                tm1 = fmaxf(tm1, fmaxf(sc[n*4+2], sc[n*4+3]));
            }
            tm0 = fmaxf(tm0, __shfl_xor_sync(0xffffffffu, tm0, 1));
            tm0 = fmaxf(tm0, __shfl_xor_sync(0xffffffffu, tm0, 2));
            tm1 = fmaxf(tm1, __shfl_xor_sync(0xffffffffu, tm1, 1));
            tm1 = fmaxf(tm1, __shfl_xor_sync(0xffffffffu, tm1, 2));
            float nm0 = fmaxf(mrow[0], tm0);
            float nm1 = fmaxf(mrow[1], tm1);
            float al0 = __expf(mrow[0] - nm0);
            float al1 = __expf(mrow[1] - nm1);
            mrow[0] = nm0; mrow[1] = nm1;

            float rs0 = 0.f, rs1 = 0.f;
            #pragma unroll
            for (int n = 0; n < 8; n++) {
                sc[n*4+0] = __expf(sc[n*4+0] - nm0);
                sc[n*4+1] = __expf(sc[n*4+1] - nm0);
                sc[n*4+2] = __expf(sc[n*4+2] - nm1);
                sc[n*4+3] = __expf(sc[n*4+3] - nm1);
                rs0 += sc[n*4+0] + sc[n*4+1];
                rs1 += sc[n*4+2] + sc[n*4+3];
            }
            rs0 += __shfl_xor_sync(0xffffffffu, rs0, 1);
            rs0 += __shfl_xor_sync(0xffffffffu, rs0, 2);
            rs1 += __shfl_xor_sync(0xffffffffu, rs1, 1);
            rs1 += __shfl_xor_sync(0xffffffffu, rs1, 2);
            lsum[0] = lsum[0]*al0 + rs0;
            lsum[1] = lsum[1]*al1 + rs1;
            #pragma unroll
            for (int n = 0; n < 8; n++) {
                O[n*4+0] *= al0; O[n*4+1] *= al0;
                O[n*4+2] *= al1; O[n*4+3] *= al1;
            }

            // ---- PV: O += P V (bf16x3; P from regs) ----
            #pragma unroll
            for (int kk = 0; kk < 4; kk++) {
                float p00 = sc[(2*kk)*4+0],   p01 = sc[(2*kk)*4+1];
                float p02 = sc[(2*kk)*4+2],   p03 = sc[(2*kk)*4+3];
                float p10 = sc[(2*kk+1)*4+0], p11 = sc[(2*kk+1)*4+1];
                float p12 = sc[(2*kk+1)*4+2], p13 = sc[(2*kk+1)*4+3];
                uint32_t pH[4], pL[4];
                pH[0] = pk2(p00, p01); pH[1] = pk2(p02, p03);
                pH[2] = pk2(p10, p11); pH[3] = pk2(p12, p13);
                {
                    __nv_bfloat162 t;
                    t = *(__nv_bfloat162*)&pH[0];
                    pL[0] = pk2(p00 - __bfloat162float(t.x), p01 - __bfloat162float(t.y));
                    t = *(__nv_bfloat162*)&pH[1];
                    pL[1] = pk2(p02 - __bfloat162float(t.x), p03 - __bfloat162float(t.y));
                    t = *(__nv_bfloat162*)&pH[2];
                    pL[2] = pk2(p10 - __bfloat162float(t.x), p11 - __bfloat162float(t.y));
                    t = *(__nv_bfloat162*)&pH[3];
                    pL[3] = pk2(p12 - __bfloat162float(t.x), p13 - __bfloat162float(t.y));
                }
                #pragma unroll
                for (int dp = 0; dp < 4; dp++) {
                    uint32_t va = kvb + 2*FKV_TB + v_rl + (uint32_t)(kk*16*FS_ROWB) + dp*32;
                    uint32_t vH[4], vL[4];
                    LDSM4T(vH, va);
                    LDSM4T(vL, va + FKV_TB);
                    float* o0 = &O[(2*dp)*4];
                    float* o1 = &O[(2*dp+1)*4];
                    MMA2(o0, pH, vH[0], vH[1]);
                    MMA2(o1, pH, vH[2], vH[3]);
                    MMA2(o0, pH, vL[0], vL[1]);
                    MMA2(o1, pH, vL[2], vL[3]);
                    MMA2(o0, pL, vH[0], vH[1]);
                    MMA2(o1, pL, vH[2], vH[3]);
                }
            }
        }
        __syncthreads();
    }

    // ---- normalize + store bf16 hi/lo to g_ah/g_al ----
    float inv0 = 1.0f / lsum[0];
    float inv1 = 1.0f / lsum[1];
    int b = bh >> 4, h = bh & 15;
    int colb = h*64 + (lane & 3)*2;
    size_t base0 = ((size_t)(b*Ss + row0g)) * Dd;
    size_t base1 = ((size_t)(b*Ss + row0g + 8)) * Dd;
    #pragma unroll
    for (int n = 0; n < 8; n++) {
        float x0 = O[n*4+0]*inv0, y0 = O[n*4+1]*inv0;
        float x1 = O[n*4+2]*inv1, y1 = O[n*4+3]*inv1;
        __nv_bfloat16 hx0 = __float2bfloat16(x0), hy0 = __float2bfloat16(y0);
        __nv_bfloat16 hx1 = __float2bfloat16(x1), hy1 = __float2bfloat16(y1);
        size_t i0 = base0 + colb + n*8;
        size_t i1 = base1 + colb + n*8;
        *(ushort2*)&g_ah[i0] = make_ushort2(__bfloat16_as_ushort(hx0), __bfloat16_as_ushort(hy0));
        *(ushort2*)&g_ah[i1] = make_ushort2(__bfloat16_as_ushort(hx1), __bfloat16_as_ushort(hy1));
        __nv_bfloat16 lx0 = __float2bfloat16(x0 - __bfloat162float(hx0));
        __nv_bfloat16 ly0 = __float2bfloat16(y0 - __bfloat162float(hy0));
        __nv_bfloat16 lx1 = __float2bfloat16(x1 - __bfloat162float(hx1));
        __nv_bfloat16 ly1 = __float2bfloat16(y1 - __bfloat162float(hy1));
        *(ushort2*)&g_al[i0] = make_ushort2(__bfloat16_as_ushort(lx0), __bfloat16_as_ushort(ly0));
        *(ushort2*)&g_al[i1] = make_ushort2(__bfloat16_as_ushort(lx1), __bfloat16_as_ushort(ly1));
    }
}

// ---------------- launch ----------------
extern "C" void kernel_launch(void* const* d_in, const int* in_sizes, int n_in,
                              void* d_out, int out_size) {
    const float* x  = (const float*)d_in[0];
    const float* Wq = (const float*)d_in[1];
    const float* bq = (const float*)d_in[2];
    const float* Wk = (const float*)d_in[3];
    const float* bk = (const float*)d_in[4];
    const float* Wv = (const float*)d_in[5];
    const float* bv = (const float*)d_in[6];
    const float* Wo = (const float*)d_in[7];
    const float* bo = (const float*)d_in[8];
    float* out = (float*)d_out;

    cudaFuncSetAttribute(gemm_mma,
                         cudaFuncAttributeMaxDynamicSharedMemorySize, G_SMEM);
    cudaFuncSetAttribute(flash_mma,
                         cudaFuncAttributeMaxDynamicSharedMemorySize, FA_SMEM);

    __nv_bfloat16 *xh, *xl, *ah, *al, *wh, *wl;
    cudaGetSymbolAddress((void**)&xh, g_xh);
    cudaGetSymbolAddress((void**)&xl, g_xl);
    cudaGetSymbolAddress((void**)&ah, g_ah);
    cudaGetSymbolAddress((void**)&al, g_al);
    cudaGetSymbolAddress((void**)&wh, g_wh);
    cudaGetSymbolAddress((void**)&wl, g_wl);

    rope_table_kernel<<<Ss, 32>>>();

    convert_kernel<<<(Mm*Dd/4)/256, 256>>>(x,  xh, xl, Mm*Dd/4);
    convert_kernel<<<(Dd*Dd/4)/256, 256>>>(Wq, wh + 0*(size_t)Dd*Dd, wl + 0*(size_t)Dd*Dd, Dd*Dd/4);
    convert_kernel<<<(Dd*Dd/4)/256, 256>>>(Wk, wh + 1*(size_t)Dd*Dd, wl + 1*(size_t)Dd*Dd, Dd*Dd/4);
    convert_kernel<<<(Dd*Dd/4)/256, 256>>>(Wv, wh + 2*(size_t)Dd*Dd, wl + 2*(size_t)Dd*Dd, Dd*Dd/4);
    convert_kernel<<<(Dd*Dd/4)/256, 256>>>(Wo, wh + 3*(size_t)Dd*Dd, wl + 3*(size_t)Dd*Dd, Dd*Dd/4);

    dim3 gg(Dd / 128, Mm / 128);   // (8, 32)
    gemm_mma<<<gg, 256, G_SMEM>>>(xh, xl, wh + 0*(size_t)Dd*Dd, wl + 0*(size_t)Dd*Dd, bq, nullptr, 0);
    gemm_mma<<<gg, 256, G_SMEM>>>(xh, xl, wh + 1*(size_t)Dd*Dd, wl + 1*(size_t)Dd*Dd, bk, nullptr, 1);
    gemm_mma<<<gg, 256, G_SMEM>>>(xh, xl, wh + 2*(size_t)Dd*Dd, wl + 2*(size_t)Dd*Dd, bv, nullptr, 2);

    rope_apply_kernel<<<dim3((Bb*Hh*Ss*32) / 256, 2), 256>>>();

    flash_mma<<<dim3(Ss / 128, Bb*Hh), 256, FA_SMEM>>>();

    gemm_mma<<<gg, 256, G_SMEM>>>(ah, al, wh + 3*(size_t)Dd*Dd, wl + 3*(size_t)Dd*Dd, bo, out, 3);
}